// round 7
// baseline (speedup 1.0000x reference)
#include <cuda_runtime.h>
#include <cuda_bf16.h>
#include <cstdint>
#include <cstdio>

// Problem constants
#define BB   8
#define SS   2048
#define DD   1024
#define KK   256
#define NFFT 2048
#define K2   512
#define SH   1024   // folded length

// ---------------- device scratch ----------------
__device__ __align__(256) float2        g_tbl[NFFT];              // cos/sin table
__device__ __align__(256) __nv_bfloat16 g_basis1f[K2 * SH];       // rows 0..255 cos(f*s), 256..511 -sin(f*s); col = s-1
__device__ __align__(256) __nv_bfloat16 g_basis2f[2 * SH * KK];   // rows 0..1023 (c/N)cos, rows 1024..2047 -(c/N)sin
__device__ __align__(256) __nv_bfloat16 g_wt[KK * KK];            // WT[j][k] = W[k][j]
__device__ __align__(256) float         g_cwr[KK * DD];           // mag*cos(ph)
__device__ __align__(256) float         g_cwi[KK * DD];           // mag*sin(ph)
__device__ __align__(256) __nv_bfloat16 g_xc[BB * SH * DD];       // x_s + x_{2048-s}
__device__ __align__(256) __nv_bfloat16 g_xd[BB * SH * DD];       // x_s - x_{2048-s}
__device__ __align__(256) __nv_bfloat16 g_xwr[BB * KK * DD];      // Re(x_weighted)
__device__ __align__(256) float         g_dpart[BB * KK * DD];    // xwr - Xr
__device__ __align__(256) __nv_bfloat16 g_delta[BB * K2 * DD];    // [deltar; deltai]

// ---------------- helpers ----------------
__device__ __forceinline__ int freq_of(int k) {
    if (k == 255) return 512;
    return (int)((double)k * (512.0 / 255.0));
}
__device__ __forceinline__ uint32_t smem_u32(const void* p) {
    return (uint32_t)__cvta_generic_to_shared(p);
}
__device__ __forceinline__ void cp_async16(void* smem_dst, const void* gmem_src) {
    asm volatile("cp.async.cg.shared.global [%0], [%1], 16;\n"
                 :: "r"(smem_u32(smem_dst)), "l"(gmem_src));
}
__device__ __forceinline__ void cp_commit() {
    asm volatile("cp.async.commit_group;\n");
}
template <int N>
__device__ __forceinline__ void cp_wait() {
    asm volatile("cp.async.wait_group %0;\n" :: "n"(N));
}

// ---------------- tiny precompute kernels ----------------
__global__ void k_tbl() {
    int m = blockIdx.x * blockDim.x + threadIdx.x;   // 2048
    float ang = (float)m * (6.28318530717958647692f / (float)NFFT);
    float sv, cv;
    sincosf(ang, &sv, &cv);
    g_tbl[m] = make_float2(cv, sv);
}

__global__ void k_basis1f() {
    int idx = blockIdx.x * blockDim.x + threadIdx.x;
    if (idx >= K2 * SH) return;
    int row = idx >> 10;
    int s   = (idx & 1023) + 1;
    int k   = row & 255;
    int f   = freq_of(k);
    float2 t = g_tbl[(f * s) & (NFFT - 1)];
    g_basis1f[idx] = __float2bfloat16((row < KK) ? t.x : -t.y);
}

__global__ void k_basis2f() {
    int idx = blockIdx.x * blockDim.x + threadIdx.x;
    if (idx >= 2 * SH * KK) return;
    int row = idx >> 8;
    int j   = idx & 255;
    int s   = row & 1023;
    int f   = freq_of(j);
    float2 t = g_tbl[(f * s) & (NFFT - 1)];
    float scale = ((f == 0) ? 1.0f : 2.0f) * (1.0f / (float)NFFT);
    g_basis2f[idx] = __float2bfloat16((row < SH) ? (scale * t.x) : (-scale * t.y));
}

__global__ void k_wt(const float* __restrict__ W) {
    int idx = blockIdx.x * blockDim.x + threadIdx.x;
    if (idx >= KK * KK) return;
    int j = idx >> 8, k = idx & 255;
    g_wt[idx] = __float2bfloat16(W[k * KK + j]);
}

__global__ void k_cw(const float* __restrict__ mag, const float* __restrict__ ph) {
    int idx = blockIdx.x * blockDim.x + threadIdx.x;   // 256K
    if (idx >= KK * DD) return;
    float sp, cp;
    sincosf(ph[idx], &sp, &cp);
    float m = mag[idx];
    g_cwr[idx] = m * cp;
    g_cwi[idx] = m * sp;
}

// ---------------- fold ----------------
__global__ void k_fold(const float* __restrict__ x) {
    int idx = blockIdx.x * blockDim.x + threadIdx.x;
    if (idx >= BB * SH * (DD / 4)) return;
    int b   = idx >> 18;
    int r   = idx & 262143;
    int srow = r >> 8;
    int d4   = (r & 255) << 2;
    int s = srow + 1;
    const float* xb = x + (size_t)b * SS * DD;
    float4 xs = *(const float4*)(xb + (size_t)s * DD + d4);
    float4 c, d;
    if (s == 1024) {
        c = xs;
        d = make_float4(0.f, 0.f, 0.f, 0.f);
    } else {
        float4 xm = *(const float4*)(xb + (size_t)(SS - s) * DD + d4);
        c = make_float4(xs.x + xm.x, xs.y + xm.y, xs.z + xm.z, xs.w + xm.w);
        d = make_float4(xs.x - xm.x, xs.y - xm.y, xs.z - xm.z, xs.w - xm.w);
    }
    size_t o = ((size_t)b * SH + srow) * DD + d4;
    *(__nv_bfloat162*)&g_xc[o]     = __floats2bfloat162_rn(c.x, c.y);
    *(__nv_bfloat162*)&g_xc[o + 2] = __floats2bfloat162_rn(c.z, c.w);
    *(__nv_bfloat162*)&g_xd[o]     = __floats2bfloat162_rn(d.x, d.y);
    *(__nv_bfloat162*)&g_xd[o + 2] = __floats2bfloat162_rn(d.z, d.w);
}

// ================= dual-accumulator GEMM engine (G1 fused + G2 fused) =================
// A tile: 256 rows x 32 k (two 128-row halves), stride 40
// B tile: 64 rows x 64+ cols (two 32-row halves), stride 72
#define BMD 128
#define BND 64
#define BKD 32
#define NSTD 3
#define AD_BYTES (256 * 40 * 2)    // 20480
#define BD_BYTES (64 * 72 * 2)     // 9216
#define GD_SMEM (NSTD * (AD_BYTES + BD_BYTES))   // 89088

// ---- G1 fused: Xr/Xi GEMM + complex weighting epilogue ----
// acc_c[k][d] = sum_s cos(f_k s) xc[s][d]    (A rows 0..127 per tile from basis1f cos block)
// acc_s[k][d] = sum_s -sin(f_k s) xd[s][d]   (A rows 128..255 from basis1f sin block)
// Xr = acc_c + x0[d]; Xi = acc_s
// xwr = Xr*cwr - Xi*cwi ; xwi = Xr*cwi + Xi*cwr
// out: g_xwr (bf16), g_dpart = xwr-Xr (fp32), g_delta[KK+k] = xwi-Xi (bf16)
__global__ __launch_bounds__(256, 2) void gemm_g1(const float* __restrict__ x)
{
    extern __shared__ __align__(16) char dsm[];

    int bz = blockIdx.z;
    int k0 = blockIdx.y * BMD;     // 0 or 128
    int n0 = blockIdx.x * BND;     // d tile
    const __nv_bfloat16* xcb = g_xc + (size_t)bz * SH * DD;
    const __nv_bfloat16* xdb = g_xd + (size_t)bz * SH * DD;
    const float* xb = x + (size_t)bz * SS * DD;

    int tid = threadIdx.x, lane = tid & 31, warp = tid >> 5;
    int wm = (warp & 3) * 32;
    int wn = (warp >> 2) * 32;

    float acc_c[2][4][4], acc_s[2][4][4];
#pragma unroll
    for (int i = 0; i < 2; i++)
#pragma unroll
        for (int j = 0; j < 4; j++)
#pragma unroll
            for (int c = 0; c < 4; c++) { acc_c[i][j][c] = 0.f; acc_s[i][j][c] = 0.f; }

    auto st_base = [&](int st) -> char* { return dsm + st * (AD_BYTES + BD_BYTES); };

    auto load_stage = [&](int s) {
        char* ap = st_base(s % NSTD);
        char* bp = ap + AD_BYTES;
        int s0k = s * BKD;   // s-slice base (col of basis1f, row of xc/xd)
#pragma unroll
        for (int i = 0; i < 4; i++) {
            int c = tid + i * 256;
            int row = c >> 2, col = (c & 3) << 3;
            int arow = (row < 128) ? (k0 + row) : (KK + k0 + row - 128);
            cp_async16(ap + (row * 40 + col) * 2, g_basis1f + (size_t)arow * SH + s0k + col);
        }
#pragma unroll
        for (int i = 0; i < 2; i++) {
            int c = tid + i * 256;
            int row = c >> 3, col = (c & 7) << 3;
            const __nv_bfloat16* src = (row < 32) ? (xcb + (size_t)(s0k + row) * DD)
                                                  : (xdb + (size_t)(s0k + row - 32) * DD);
            cp_async16(bp + (row * 72 + col) * 2, src + n0 + col);
        }
        cp_commit();
    };

    load_stage(0);
    load_stage(1);

    const int nt = SH / BKD;   // 32
    for (int kt = 0; kt < nt; kt++) {
        cp_wait<1>();
        __syncthreads();
        if (kt + 2 < nt) load_stage(kt + 2);
        else             cp_commit();

        char* ap = st_base(kt % NSTD);
        char* bp = ap + AD_BYTES;

#pragma unroll
        for (int kk = 0; kk < BKD; kk += 16) {
            uint32_t afc[2][4], afs[2][4], bfr[4][2], bfi[4][2];
            int ar = wm + (lane & 15);
            int ac = kk + ((lane >> 4) << 3);
#pragma unroll
            for (int mi = 0; mi < 2; mi++) {
                uint32_t a1 = smem_u32(ap + ((ar + mi * 16) * 40 + ac) * 2);
                asm volatile("ldmatrix.sync.aligned.m8n8.x4.shared.b16 {%0,%1,%2,%3}, [%4];"
                             : "=r"(afc[mi][0]), "=r"(afc[mi][1]), "=r"(afc[mi][2]), "=r"(afc[mi][3])
                             : "r"(a1));
                uint32_t a2 = smem_u32(ap + ((128 + ar + mi * 16) * 40 + ac) * 2);
                asm volatile("ldmatrix.sync.aligned.m8n8.x4.shared.b16 {%0,%1,%2,%3}, [%4];"
                             : "=r"(afs[mi][0]), "=r"(afs[mi][1]), "=r"(afs[mi][2]), "=r"(afs[mi][3])
                             : "r"(a2));
            }
            int br = kk + (lane & 15);
#pragma unroll
            for (int ni = 0; ni < 4; ni++) {
                uint32_t b1 = smem_u32(bp + (br * 72 + wn + ni * 8) * 2);
                asm volatile("ldmatrix.sync.aligned.m8n8.x2.trans.shared.b16 {%0,%1}, [%2];"
                             : "=r"(bfr[ni][0]), "=r"(bfr[ni][1]) : "r"(b1));
                uint32_t b2 = smem_u32(bp + ((32 + br) * 72 + wn + ni * 8) * 2);
                asm volatile("ldmatrix.sync.aligned.m8n8.x2.trans.shared.b16 {%0,%1}, [%2];"
                             : "=r"(bfi[ni][0]), "=r"(bfi[ni][1]) : "r"(b2));
            }
#pragma unroll
            for (int mi = 0; mi < 2; mi++)
#pragma unroll
                for (int ni = 0; ni < 4; ni++) {
                    float* dc = acc_c[mi][ni];
                    asm volatile(
                        "mma.sync.aligned.m16n8k16.row.col.f32.bf16.bf16.f32 "
                        "{%0,%1,%2,%3}, {%4,%5,%6,%7}, {%8,%9}, {%0,%1,%2,%3};"
                        : "+f"(dc[0]), "+f"(dc[1]), "+f"(dc[2]), "+f"(dc[3])
                        : "r"(afc[mi][0]), "r"(afc[mi][1]), "r"(afc[mi][2]), "r"(afc[mi][3]),
                          "r"(bfr[ni][0]), "r"(bfr[ni][1]));
                    float* ds = acc_s[mi][ni];
                    asm volatile(
                        "mma.sync.aligned.m16n8k16.row.col.f32.bf16.bf16.f32 "
                        "{%0,%1,%2,%3}, {%4,%5,%6,%7}, {%8,%9}, {%0,%1,%2,%3};"
                        : "+f"(ds[0]), "+f"(ds[1]), "+f"(ds[2]), "+f"(ds[3])
                        : "r"(afs[mi][0]), "r"(afs[mi][1]), "r"(afs[mi][2]), "r"(afs[mi][3]),
                          "r"(bfi[ni][0]), "r"(bfi[ni][1]));
                }
        }
    }

    // epilogue: complex weighting, write xwr / dpart / delta_i
    int g = lane >> 2, t2 = (lane & 3) << 1;
    __nv_bfloat16* xwrb = g_xwr + (size_t)bz * KK * DD;
    float* dpb = g_dpart + (size_t)bz * KK * DD;
    __nv_bfloat16* dib = g_delta + (size_t)bz * K2 * DD + (size_t)KK * DD;
#pragma unroll
    for (int ni = 0; ni < 4; ni++) {
        int col = n0 + wn + ni * 8 + t2;
        float2 x0v = *(const float2*)(xb + col);   // x row 0
#pragma unroll
        for (int mi = 0; mi < 2; mi++) {
            float* dc = acc_c[mi][ni];
            float* ds = acc_s[mi][ni];
#pragma unroll
            for (int h = 0; h < 2; h++) {
                int k = k0 + wm + mi * 16 + g + h * 8;
                size_t o = (size_t)k * DD + col;
                float2 wr = *(const float2*)(g_cwr + o);
                float2 wi = *(const float2*)(g_cwi + o);
                float Xr0 = dc[2 * h]     + x0v.x;
                float Xr1 = dc[2 * h + 1] + x0v.y;
                float Xi0 = ds[2 * h];
                float Xi1 = ds[2 * h + 1];
                float xwr0 = Xr0 * wr.x - Xi0 * wi.x;
                float xwr1 = Xr1 * wr.y - Xi1 * wi.y;
                float xwi0 = Xr0 * wi.x + Xi0 * wr.x;
                float xwi1 = Xr1 * wi.y + Xi1 * wr.y;
                *(__nv_bfloat162*)&xwrb[o] = __floats2bfloat162_rn(xwr0, xwr1);
                *(float2*)&dpb[o]          = make_float2(xwr0 - Xr0, xwr1 - Xr1);
                *(__nv_bfloat162*)&dib[o]  = __floats2bfloat162_rn(xwi0 - Xi0, xwi1 - Xi1);
            }
        }
    }
}

// ---- G2 fused: folded irfft, mirror + residual epilogue (unchanged from R6) ----
__global__ __launch_bounds__(256, 2) void gemm_g2(
    const float* __restrict__ x, float* __restrict__ out)
{
    extern __shared__ __align__(16) char dsm[];

    int bz = blockIdx.z;
    int s0 = blockIdx.y * BMD;
    int n0 = blockIdx.x * BND;
    const __nv_bfloat16* Adel = g_delta + (size_t)bz * K2 * DD;
    const float* xb = x + (size_t)bz * SS * DD;
    float* ob = out + (size_t)bz * SS * DD;

    int tid = threadIdx.x, lane = tid & 31, warp = tid >> 5;
    int wm = (warp & 3) * 32;
    int wn = (warp >> 2) * 32;

    float acc_c[2][4][4], acc_s[2][4][4];
#pragma unroll
    for (int i = 0; i < 2; i++)
#pragma unroll
        for (int j = 0; j < 4; j++)
#pragma unroll
            for (int c = 0; c < 4; c++) { acc_c[i][j][c] = 0.f; acc_s[i][j][c] = 0.f; }

    auto st_base = [&](int st) -> char* { return dsm + st * (AD_BYTES + BD_BYTES); };

    auto load_stage = [&](int s) {
        char* ap = st_base(s % NSTD);
        char* bp = ap + AD_BYTES;
        int k0 = s * BKD;
#pragma unroll
        for (int i = 0; i < 4; i++) {
            int c = tid + i * 256;
            int row = c >> 2, col = (c & 3) << 3;
            int srow = (row < 128) ? (s0 + row) : (SH + s0 + row - 128);
            cp_async16(ap + (row * 40 + col) * 2, g_basis2f + (size_t)srow * KK + k0 + col);
        }
#pragma unroll
        for (int i = 0; i < 2; i++) {
            int c = tid + i * 256;
            int row = c >> 3, col = (c & 7) << 3;
            int drow = (row < 32) ? (k0 + row) : (KK + k0 + row - 32);
            cp_async16(bp + (row * 72 + col) * 2, Adel + (size_t)drow * DD + n0 + col);
        }
        cp_commit();
    };

    load_stage(0);
    load_stage(1);

    const int nt = KK / BKD;   // 8
    for (int kt = 0; kt < nt; kt++) {
        cp_wait<1>();
        __syncthreads();
        if (kt + 2 < nt) load_stage(kt + 2);
        else             cp_commit();

        char* ap = st_base(kt % NSTD);
        char* bp = ap + AD_BYTES;

#pragma unroll
        for (int kk = 0; kk < BKD; kk += 16) {
            uint32_t afc[2][4], afs[2][4], bfr[4][2], bfi[4][2];
            int ar = wm + (lane & 15);
            int ac = kk + ((lane >> 4) << 3);
#pragma unroll
            for (int mi = 0; mi < 2; mi++) {
                uint32_t a1 = smem_u32(ap + ((ar + mi * 16) * 40 + ac) * 2);
                asm volatile("ldmatrix.sync.aligned.m8n8.x4.shared.b16 {%0,%1,%2,%3}, [%4];"
                             : "=r"(afc[mi][0]), "=r"(afc[mi][1]), "=r"(afc[mi][2]), "=r"(afc[mi][3])
                             : "r"(a1));
                uint32_t a2 = smem_u32(ap + ((128 + ar + mi * 16) * 40 + ac) * 2);
                asm volatile("ldmatrix.sync.aligned.m8n8.x4.shared.b16 {%0,%1,%2,%3}, [%4];"
                             : "=r"(afs[mi][0]), "=r"(afs[mi][1]), "=r"(afs[mi][2]), "=r"(afs[mi][3])
                             : "r"(a2));
            }
            int br = kk + (lane & 15);
#pragma unroll
            for (int ni = 0; ni < 4; ni++) {
                uint32_t b1 = smem_u32(bp + (br * 72 + wn + ni * 8) * 2);
                asm volatile("ldmatrix.sync.aligned.m8n8.x2.trans.shared.b16 {%0,%1}, [%2];"
                             : "=r"(bfr[ni][0]), "=r"(bfr[ni][1]) : "r"(b1));
                uint32_t b2 = smem_u32(bp + ((32 + br) * 72 + wn + ni * 8) * 2);
                asm volatile("ldmatrix.sync.aligned.m8n8.x2.trans.shared.b16 {%0,%1}, [%2];"
                             : "=r"(bfi[ni][0]), "=r"(bfi[ni][1]) : "r"(b2));
            }
#pragma unroll
            for (int mi = 0; mi < 2; mi++)
#pragma unroll
                for (int ni = 0; ni < 4; ni++) {
                    float* dc = acc_c[mi][ni];
                    asm volatile(
                        "mma.sync.aligned.m16n8k16.row.col.f32.bf16.bf16.f32 "
                        "{%0,%1,%2,%3}, {%4,%5,%6,%7}, {%8,%9}, {%0,%1,%2,%3};"
                        : "+f"(dc[0]), "+f"(dc[1]), "+f"(dc[2]), "+f"(dc[3])
                        : "r"(afc[mi][0]), "r"(afc[mi][1]), "r"(afc[mi][2]), "r"(afc[mi][3]),
                          "r"(bfr[ni][0]), "r"(bfr[ni][1]));
                    float* ds = acc_s[mi][ni];
                    asm volatile(
                        "mma.sync.aligned.m16n8k16.row.col.f32.bf16.bf16.f32 "
                        "{%0,%1,%2,%3}, {%4,%5,%6,%7}, {%8,%9}, {%0,%1,%2,%3};"
                        : "+f"(ds[0]), "+f"(ds[1]), "+f"(ds[2]), "+f"(ds[3])
                        : "r"(afs[mi][0]), "r"(afs[mi][1]), "r"(afs[mi][2]), "r"(afs[mi][3]),
                          "r"(bfi[ni][0]), "r"(bfi[ni][1]));
                }
        }
    }

    int g = lane >> 2, t2 = (lane & 3) << 1;
#pragma unroll
    for (int mi = 0; mi < 2; mi++) {
#pragma unroll
        for (int ni = 0; ni < 4; ni++) {
            float* dc = acc_c[mi][ni];
            float* ds = acc_s[mi][ni];
            int col = n0 + wn + ni * 8 + t2;
#pragma unroll
            for (int h = 0; h < 2; h++) {
                int s = s0 + wm + mi * 16 + g + h * 8;
                float vc0 = dc[2 * h], vc1 = dc[2 * h + 1];
                float vs0 = ds[2 * h], vs1 = ds[2 * h + 1];
                float2 xv = *(const float2*)(xb + (size_t)s * DD + col);
                *(float2*)(ob + (size_t)s * DD + col) =
                    make_float2(vc0 + vs0 + 2.f * xv.x, vc1 + vs1 + 2.f * xv.y);
                if (s > 0) {
                    float2 xm = *(const float2*)(xb + (size_t)(SS - s) * DD + col);
                    *(float2*)(ob + (size_t)(SS - s) * DD + col) =
                        make_float2(vc0 - vs0 + 2.f * xm.x, vc1 - vs1 + 2.f * xm.y);
                }
            }
        }
    }
}

// ---------------- interference GEMM (mma.sync, C = aux + 0.1*acc, bf16 out) ----
#define BM 128
#define BN 128
#define BKg 32
#define NSTG 4
#define A_BYTES (BM * 40 * 2)
#define B_BYTES (BKg * 136 * 2)
#define GEMM_SMEM (NSTG * (A_BYTES + B_BYTES))

__global__ __launch_bounds__(256, 2) void gemm_mma1(
    const __nv_bfloat16* __restrict__ A, int ldA,
    const __nv_bfloat16* __restrict__ Bm, size_t sB, int ldB,
    __nv_bfloat16* __restrict__ Cv, size_t sC, int ldC,
    const float* __restrict__ aux, size_t sAux,
    int Kdim)
{
    extern __shared__ __align__(16) char dsm[];

    int bz = blockIdx.z;
    int bm = blockIdx.y * BM;
    int bn = blockIdx.x * BN;
    const __nv_bfloat16* Ab = A;
    const __nv_bfloat16* Bb = Bm + sB * bz;

    int tid = threadIdx.x, lane = tid & 31, warp = tid >> 5;
    int wm = (warp & 1) * 64;
    int wn = (warp >> 1) * 32;

    int a_r0 = tid >> 2;
    int a_c  = (tid & 3) << 3;
    int b_r0 = tid >> 4;
    int b_c  = (tid & 15) << 3;

    float acc[4][4][4];
#pragma unroll
    for (int i = 0; i < 4; i++)
#pragma unroll
        for (int j = 0; j < 4; j++)
#pragma unroll
            for (int c = 0; c < 4; c++) acc[i][j][c] = 0.f;

    int nt = Kdim / BKg;

    auto a_base = [&](int st) -> char* { return dsm + st * A_BYTES; };
    auto b_base = [&](int st) -> char* { return dsm + NSTG * A_BYTES + st * B_BYTES; };

    auto load_stage = [&](int s) {
        char* ap = a_base(s & (NSTG - 1));
        char* bp = b_base(s & (NSTG - 1));
        int k0 = s * BKg;
        cp_async16(ap + (a_r0 * 40 + a_c) * 2,        Ab + (size_t)(bm + a_r0) * ldA + k0 + a_c);
        cp_async16(ap + ((a_r0 + 64) * 40 + a_c) * 2, Ab + (size_t)(bm + a_r0 + 64) * ldA + k0 + a_c);
        cp_async16(bp + (b_r0 * 136 + b_c) * 2,        Bb + (size_t)(k0 + b_r0) * ldB + bn + b_c);
        cp_async16(bp + ((b_r0 + 16) * 136 + b_c) * 2, Bb + (size_t)(k0 + b_r0 + 16) * ldB + bn + b_c);
        cp_commit();
    };

#pragma unroll
    for (int i = 0; i < NSTG - 1; i++) load_stage(i);

    for (int kt = 0; kt < nt; kt++) {
        cp_wait<NSTG - 2>();
        __syncthreads();
        if (kt + NSTG - 1 < nt) load_stage(kt + NSTG - 1);
        else                    cp_commit();

        char* ap = a_base(kt & (NSTG - 1));
        char* bp = b_base(kt & (NSTG - 1));

#pragma unroll
        for (int kk = 0; kk < BKg; kk += 16) {
            uint32_t af[4][4], bf[4][2];
            int ar = wm + (lane & 15);
            int ac = kk + ((lane >> 4) << 3);
#pragma unroll
            for (int mi = 0; mi < 4; mi++) {
                uint32_t ad = smem_u32(ap + ((ar + mi * 16) * 40 + ac) * 2);
                asm volatile("ldmatrix.sync.aligned.m8n8.x4.shared.b16 {%0,%1,%2,%3}, [%4];"
                             : "=r"(af[mi][0]), "=r"(af[mi][1]), "=r"(af[mi][2]), "=r"(af[mi][3])
                             : "r"(ad));
            }
            int br = kk + (lane & 15);
#pragma unroll
            for (int ni = 0; ni < 4; ni++) {
                uint32_t bd = smem_u32(bp + (br * 136 + wn + ni * 8) * 2);
                asm volatile("ldmatrix.sync.aligned.m8n8.x2.trans.shared.b16 {%0,%1}, [%2];"
                             : "=r"(bf[ni][0]), "=r"(bf[ni][1]) : "r"(bd));
            }
#pragma unroll
            for (int mi = 0; mi < 4; mi++)
#pragma unroll
                for (int ni = 0; ni < 4; ni++) {
                    float* d = acc[mi][ni];
                    asm volatile(
                        "mma.sync.aligned.m16n8k16.row.col.f32.bf16.bf16.f32 "
                        "{%0,%1,%2,%3}, {%4,%5,%6,%7}, {%8,%9}, {%0,%1,%2,%3};"
                        : "+f"(d[0]), "+f"(d[1]), "+f"(d[2]), "+f"(d[3])
                        : "r"(af[mi][0]), "r"(af[mi][1]), "r"(af[mi][2]), "r"(af[mi][3]),
                          "r"(bf[ni][0]), "r"(bf[ni][1]));
                }
        }
    }

    int g = lane >> 2, t2 = (lane & 3) << 1;
#pragma unroll
    for (int mi = 0; mi < 4; mi++) {
#pragma unroll
        for (int ni = 0; ni < 4; ni++) {
            int row0 = bm + wm + mi * 16 + g;
            int col  = bn + wn + ni * 8 + t2;
            float* d = acc[mi][ni];
            __nv_bfloat16* Cp = Cv + sC * bz;
            const float* ax = aux + sAux * bz;
            float2 a0 = *(const float2*)&ax[(size_t)row0 * ldC + col];
            float2 a1 = *(const float2*)&ax[(size_t)(row0 + 8) * ldC + col];
            *(__nv_bfloat162*)&Cp[(size_t)row0 * ldC + col] =
                __floats2bfloat162_rn(a0.x + 0.1f * d[0], a0.y + 0.1f * d[1]);
            *(__nv_bfloat162*)&Cp[(size_t)(row0 + 8) * ldC + col] =
                __floats2bfloat162_rn(a1.x + 0.1f * d[2], a1.y + 0.1f * d[3]);
        }
    }
}

// ---------------- row 1024 (Nyquist-fold row): pre-LN value ----------------
__global__ void k_row1024(const float* __restrict__ x, float* __restrict__ out) {
    int b = blockIdx.y;
    int c = blockIdx.x * 256 + threadIdx.x;
    const __nv_bfloat16* dr = g_delta + (size_t)b * K2 * DD;
    float acc = 0.f;
#pragma unroll 4
    for (int k = 0; k < KK; k++) {
        int f = freq_of(k);
        float w = ((f == 0) ? 1.0f : 2.0f) * (1.0f / (float)NFFT);
        if (f & 1) w = -w;
        acc += w * __bfloat162float(dr[(size_t)k * DD + c]);
    }
    size_t o = ((size_t)b * SS + SH) * DD + c;
    out[o] = acc + 2.f * x[o];
}

// ---------------- LayerNorm over D=1024, in place ----------------
__global__ void k_ln(float* __restrict__ y, const float* __restrict__ gamma,
                     const float* __restrict__ beta) {
    int row = blockIdx.x;
    float4* p = (float4*)(y + (size_t)row * DD);
    int t = threadIdx.x;
    float4 v = p[t];
    float s1 = v.x + v.y + v.z + v.w;
    float s2 = v.x * v.x + v.y * v.y + v.z * v.z + v.w * v.w;
#pragma unroll
    for (int o = 16; o > 0; o >>= 1) {
        s1 += __shfl_down_sync(0xffffffffu, s1, o);
        s2 += __shfl_down_sync(0xffffffffu, s2, o);
    }
    __shared__ float r1[8], r2[8];
    int w = t >> 5, l = t & 31;
    if (l == 0) { r1[w] = s1; r2[w] = s2; }
    __syncthreads();
    float mu = 0.f, m2 = 0.f;
#pragma unroll
    for (int i = 0; i < 8; i++) { mu += r1[i]; m2 += r2[i]; }
    mu *= (1.0f / (float)DD);
    float var = m2 * (1.0f / (float)DD) - mu * mu;
    float rs = rsqrtf(var + 1e-5f);
    float4 g = ((const float4*)gamma)[t];
    float4 bb = ((const float4*)beta)[t];
    v.x = (v.x - mu) * rs * g.x + bb.x;
    v.y = (v.y - mu) * rs * g.y + bb.y;
    v.z = (v.z - mu) * rs * g.z + bb.z;
    v.w = (v.w - mu) * rs * g.w + bb.w;
    p[t] = v;
}

// ---------------- launch ----------------
extern "C" void kernel_launch(void* const* d_in, const int* in_sizes, int n_in,
                              void* d_out, int out_size) {
    const float* x     = (const float*)d_in[0];
    const float* mag   = (const float*)d_in[1];
    const float* ph    = (const float*)d_in[2];
    const float* W     = (const float*)d_in[3];
    const float* gamma = (const float*)d_in[4];
    const float* beta  = (const float*)d_in[5];
    float* out = (float*)d_out;

    void *p_wt, *p_xwr, *p_dp, *p_dl;
    cudaGetSymbolAddress(&p_wt, g_wt);
    cudaGetSymbolAddress(&p_xwr, g_xwr);
    cudaGetSymbolAddress(&p_dp, g_dpart);
    cudaGetSymbolAddress(&p_dl, g_delta);

    cudaFuncSetAttribute(gemm_g1, cudaFuncAttributeMaxDynamicSharedMemorySize, GD_SMEM);
    cudaFuncSetAttribute(gemm_g2, cudaFuncAttributeMaxDynamicSharedMemorySize, GD_SMEM);
    cudaFuncSetAttribute(gemm_mma1, cudaFuncAttributeMaxDynamicSharedMemorySize, GEMM_SMEM);

    // 1. precompute: table, bases (gather), wt, cw, fold
    k_tbl<<<NFFT / 256, 256>>>();
    k_basis1f<<<(K2 * SH) / 256, 256>>>();
    k_basis2f<<<(2 * SH * KK) / 256, 256>>>();
    k_wt<<<(KK * KK) / 256, 256>>>(W);
    k_cw<<<(KK * DD) / 256, 256>>>(mag, ph);
    k_fold<<<(BB * SH * (DD / 4)) / 256, 256>>>(x);

    // 2. G1 fused: Xr/Xi + complex weighting -> xwr, dpart, delta_i
    gemm_g1<<<dim3(DD / BND, KK / BMD, BB), 256, GD_SMEM>>>(x);

    // 3. interference: deltar[b] = dpart + 0.1 * (WT @ xwr[b])
    gemm_mma1<<<dim3(DD / BN, KK / BM, BB), 256, GEMM_SMEM>>>(
        (const __nv_bfloat16*)p_wt, KK,
        (const __nv_bfloat16*)p_xwr, (size_t)KK * DD, DD,
        (__nv_bfloat16*)p_dl, (size_t)K2 * DD, DD,
        (const float*)p_dp, (size_t)KK * DD,
        KK);

    // 4. row 1024 (reads deltar)
    k_row1024<<<dim3(4, BB), 256>>>(x, out);

    // 5. G2 fused: out rows 0..1023, 1025..2047 (pre-LN), mirror + residual inline
    gemm_g2<<<dim3(DD / BND, SH / BMD, BB), 256, GD_SMEM>>>(x, out);

    // 6. LayerNorm in place
    k_ln<<<BB * SS, 256>>>(out, gamma, beta);
}